// round 1
// baseline (speedup 1.0000x reference)
#include <cuda_runtime.h>
#include <cstdint>

// GraphFullConvolution: out[n,m,o] = sum_k sum_f x[n, idx[m,k], f] * iv[m,k] * W[k,f,o] + bias[o]
// Shapes: N=16, M=65536, FIN=32, FOUT=32, K=7
static constexpr int N_   = 16;
static constexpr int M_   = 65536;
static constexpr int FIN  = 32;
static constexpr int FOUT = 32;
static constexpr int K_   = 7;
static constexpr int TILE_R = 128;          // rows (m) per block
static constexpr int AS_STRIDE = TILE_R + 4; // 132 floats: 16B-aligned row stride, pad vs bank conflicts

// Packed fp32x2 FMA (sm_103a FFMA2 path; only reachable via PTX fma.rn.f32x2)
__device__ __forceinline__ void ffma2(float2& c, float2 a, float2 b) {
    asm volatile(
        "{\n\t"
        ".reg .b64 ra, rb, rc;\n\t"
        "mov.b64 ra, {%2, %3};\n\t"
        "mov.b64 rb, {%4, %5};\n\t"
        "mov.b64 rc, {%0, %1};\n\t"
        "fma.rn.f32x2 rc, ra, rb, rc;\n\t"
        "mov.b64 {%0, %1}, rc;\n\t"
        "}"
        : "+f"(c.x), "+f"(c.y)
        : "f"(a.x), "f"(a.y), "f"(b.x), "f"(b.y));
}

__global__ void __launch_bounds__(128)
gfc_kernel(const float* __restrict__ x,
           const float* __restrict__ w,
           const float* __restrict__ bias,
           const int*   __restrict__ idxl,
           const float* __restrict__ ivv,
           float*       __restrict__ out)
{
    __shared__ float As[FIN][AS_STRIDE];   // transposed gathered tile: As[f][row], ~16.9 KB
    __shared__ float Bs[FIN][FOUT];        // W[k] chunk, 4 KB
    __shared__ int   sIdx[TILE_R * K_];    // 3.5 KB
    __shared__ float sIv [TILE_R * K_];    // 3.5 KB
    __shared__ float sBias[FOUT];

    const int tid = threadIdx.x;
    const int m0  = blockIdx.x * TILE_R;
    const int n   = blockIdx.y;

    // Stage indices / scales for this m-tile (contiguous in gmem)
    #pragma unroll
    for (int i = tid; i < TILE_R * K_; i += 128) {
        sIdx[i] = idxl[m0 * K_ + i];
        sIv[i]  = ivv [m0 * K_ + i];
    }
    if (tid < FOUT) sBias[tid] = bias[tid];

    // Thread tile: 4 rows x 8 cols. 32 row-groups x 4 col-groups = 128 threads.
    const int rg = tid >> 2;   // 0..31 -> rows 4*rg .. 4*rg+3
    const int cg = tid & 3;    // 0..3  -> cols 8*cg .. 8*cg+7

    // acc[p][j]: p packs local rows (2p, 2p+1) as float2, col j (0..7)
    float2 acc[2][8];
    #pragma unroll
    for (int p = 0; p < 2; ++p)
        #pragma unroll
        for (int j = 0; j < 8; ++j)
            acc[p][j] = make_float2(0.f, 0.f);

    const float4* x4 = reinterpret_cast<const float4*>(x);
    const int xbase4 = n * (M_ * 8);     // float4 units per n-slice (fits int)

    const int grow = tid >> 3;           // gather: 16 rows per pass, 8 segs per row
    const int gseg = tid & 7;

    for (int k = 0; k < K_; ++k) {
        __syncthreads();  // previous iteration's As/Bs reads done

        // Stage W[k] (f-major, o contiguous)
        #pragma unroll
        for (int i = tid; i < FIN * FOUT; i += 128)
            (&Bs[0][0])[i] = w[k * (FIN * FOUT) + i];

        // Gather + scale into transposed As: 128 rows x 32 floats
        #pragma unroll
        for (int pass = 0; pass < 8; ++pass) {
            const int row = pass * 16 + grow;
            const int src = sIdx[row * K_ + k];
            const float sc = sIv[row * K_ + k];
            float4 v = x4[xbase4 + src * 8 + gseg];
            const int f = gseg * 4;
            As[f + 0][row] = v.x * sc;
            As[f + 1][row] = v.y * sc;
            As[f + 2][row] = v.z * sc;
            As[f + 3][row] = v.w * sc;
        }
        __syncthreads();

        // Register-tiled GEMM over this k-chunk (reduction dim f = 32)
        #pragma unroll
        for (int f = 0; f < FIN; ++f) {
            const float4 a  = *reinterpret_cast<const float4*>(&As[f][rg * 4]);
            const float4 b0 = *reinterpret_cast<const float4*>(&Bs[f][cg * 8]);
            const float4 b1 = *reinterpret_cast<const float4*>(&Bs[f][cg * 8 + 4]);
            const float2 a01 = make_float2(a.x, a.y);
            const float2 a23 = make_float2(a.z, a.w);
            float bb[8] = {b0.x, b0.y, b0.z, b0.w, b1.x, b1.y, b1.z, b1.w};
            #pragma unroll
            for (int j = 0; j < 8; ++j) {
                const float2 bj = make_float2(bb[j], bb[j]);
                ffma2(acc[0][j], a01, bj);
                ffma2(acc[1][j], a23, bj);
            }
        }
    }

    // Epilogue: add bias, write 4 rows x 8 cols per thread (float4 stores)
    const int outbase = (n * M_ + m0) * FOUT;   // max 2^25, fits int
    #pragma unroll
    for (int p = 0; p < 2; ++p) {
        #pragma unroll
        for (int comp = 0; comp < 2; ++comp) {
            const int lr = 2 * p + comp;
            float* orow = out + outbase + (4 * rg + lr) * FOUT + 8 * cg;
            float4 v0, v1;
            v0.x = (comp ? acc[p][0].y : acc[p][0].x) + sBias[8 * cg + 0];
            v0.y = (comp ? acc[p][1].y : acc[p][1].x) + sBias[8 * cg + 1];
            v0.z = (comp ? acc[p][2].y : acc[p][2].x) + sBias[8 * cg + 2];
            v0.w = (comp ? acc[p][3].y : acc[p][3].x) + sBias[8 * cg + 3];
            v1.x = (comp ? acc[p][4].y : acc[p][4].x) + sBias[8 * cg + 4];
            v1.y = (comp ? acc[p][5].y : acc[p][5].x) + sBias[8 * cg + 5];
            v1.z = (comp ? acc[p][6].y : acc[p][6].x) + sBias[8 * cg + 6];
            v1.w = (comp ? acc[p][7].y : acc[p][7].x) + sBias[8 * cg + 7];
            reinterpret_cast<float4*>(orow)[0] = v0;
            reinterpret_cast<float4*>(orow)[1] = v1;
        }
    }
}

extern "C" void kernel_launch(void* const* d_in, const int* in_sizes, int n_in,
                              void* d_out, int out_size)
{
    const float* x    = (const float*)d_in[0];   // (16, 65536, 32) f32
    const float* wgt  = (const float*)d_in[1];   // (7, 32, 32) f32
    const float* bias = (const float*)d_in[2];   // (32,) f32
    const int*   idx  = (const int*)  d_in[3];   // (65536*7,) i32
    const float* iv   = (const float*)d_in[4];   // (65536, 7) f32
    float* out = (float*)d_out;                  // (16, 65536, 32) f32

    dim3 grid(M_ / TILE_R, N_, 1);               // (512, 16)
    dim3 block(128, 1, 1);
    gfc_kernel<<<grid, block>>>(x, wgt, bias, idx, iv, out);
}

// round 2
// speedup vs baseline: 1.2675x; 1.2675x over previous
#include <cuda_runtime.h>
#include <cstdint>

// out[n,m,o] = sum_k sum_f x[n, idx[m,k], f] * iv[m,k] * W[k,f,o] + bias[o]
// N=16, M=65536, FIN=FOUT=32, K=7
static constexpr int N_   = 16;
static constexpr int M_   = 65536;
static constexpr int FIN  = 32;
static constexpr int FOUT = 32;
static constexpr int K_   = 7;
static constexpr int TILE_R = 256;            // rows (m) per block
static constexpr int AS_S   = 260;            // row stride (floats): 16B-aligned, mod32=4

// Packed fp32x2 FMA (sm_103a FFMA2; only reachable via PTX fma.rn.f32x2)
__device__ __forceinline__ void ffma2(float2& c, float2 a, float2 b) {
    asm volatile(
        "{\n\t"
        ".reg .b64 ra, rb, rc;\n\t"
        "mov.b64 ra, {%2, %3};\n\t"
        "mov.b64 rb, {%4, %5};\n\t"
        "mov.b64 rc, {%0, %1};\n\t"
        "fma.rn.f32x2 rc, ra, rb, rc;\n\t"
        "mov.b64 {%0, %1}, rc;\n\t"
        "}"
        : "+f"(c.x), "+f"(c.y)
        : "f"(a.x), "f"(a.y), "f"(b.x), "f"(b.y));
}

__global__ void __launch_bounds__(128)
gfc_kernel(const float* __restrict__ x,
           const float* __restrict__ w,
           const float* __restrict__ bias,
           const int*   __restrict__ idxl,
           const float* __restrict__ ivv,
           float*       __restrict__ out)
{
    __shared__ float As[FIN][AS_S];   // transposed gathered tile As[f][row], 33.3 KB
    __shared__ float Bs[FIN][FOUT];   // W[k], 4 KB

    const int tid = threadIdx.x;
    const int m0  = blockIdx.x * TILE_R;
    const int n   = blockIdx.y;

    const int wrp = tid >> 5;
    const int lan = tid & 31;
    // Gather mapping: per warp 8 rows x 4 seg-pairs (2-way STS banks instead of 4-way)
    const int gr = lan >> 2;          // row-in-group 0..7
    const int gs = lan & 3;           // segment pair 0..3 -> float4 segs gs and gs+4

    // GEMM mapping: thread owns rows {4rg..4rg+3} U {4rg+128..}, cols 8*cg..
    const int rg = tid >> 2;          // 0..31
    const int cg = tid & 3;           // 0..3

    // acc[h][p][j]: h = row half (0:+0, 1:+128), p packs rows (2p,2p+1), col j
    float2 acc[2][2][8];
    #pragma unroll
    for (int h = 0; h < 2; ++h)
        #pragma unroll
        for (int p = 0; p < 2; ++p)
            #pragma unroll
            for (int j = 0; j < 8; ++j)
                acc[h][p][j] = make_float2(0.f, 0.f);

    const float4* x4 = reinterpret_cast<const float4*>(x);
    const int xb = n * (M_ * 8);

    for (int k = 0; k < K_; ++k) {
        if (k) __syncthreads();       // prior GEMM reads of As/Bs done

        // Stage W[k] (1024 floats = 256 float4)
        {
            const float4* wk = reinterpret_cast<const float4*>(w + k * (FIN * FOUT));
            float4* bs4 = reinterpret_cast<float4*>(&Bs[0][0]);
            bs4[tid]       = wk[tid];
            bs4[tid + 128] = wk[tid + 128];
        }

        // Gather + scale + transpose-store: 256 rows x 32 f
        #pragma unroll
        for (int p = 0; p < 8; ++p) {
            const int row = p * 32 + wrp * 8 + gr;
            const int m   = m0 + row;
            const int src = __ldg(&idxl[m * K_ + k]);
            const float sc = __ldg(&ivv[m * K_ + k]);
            const float4 v0 = x4[xb + src * 8 + gs];
            const float4 v1 = x4[xb + src * 8 + gs + 4];
            const int f0 = gs * 4;
            As[f0 +  0][row] = v0.x * sc;
            As[f0 +  1][row] = v0.y * sc;
            As[f0 +  2][row] = v0.z * sc;
            As[f0 +  3][row] = v0.w * sc;
            As[f0 + 16][row] = v1.x * sc;
            As[f0 + 17][row] = v1.y * sc;
            As[f0 + 18][row] = v1.z * sc;
            As[f0 + 19][row] = v1.w * sc;
        }
        __syncthreads();

        // Register-tiled GEMM: 8 rows x 8 cols per thread over f=0..31
        #pragma unroll 8
        for (int f = 0; f < FIN; ++f) {
            const float4 a0 = *reinterpret_cast<const float4*>(&As[f][rg * 4]);
            const float4 a1 = *reinterpret_cast<const float4*>(&As[f][rg * 4 + 128]);
            const float4 b0 = *reinterpret_cast<const float4*>(&Bs[f][cg * 8]);
            const float4 b1 = *reinterpret_cast<const float4*>(&Bs[f][cg * 8 + 4]);
            float2 ar[2][2];
            ar[0][0] = make_float2(a0.x, a0.y);
            ar[0][1] = make_float2(a0.z, a0.w);
            ar[1][0] = make_float2(a1.x, a1.y);
            ar[1][1] = make_float2(a1.z, a1.w);
            const float bb[8] = {b0.x, b0.y, b0.z, b0.w, b1.x, b1.y, b1.z, b1.w};
            #pragma unroll
            for (int j = 0; j < 8; ++j) {
                const float2 bj = make_float2(bb[j], bb[j]);
                #pragma unroll
                for (int h = 0; h < 2; ++h) {
                    ffma2(acc[h][0][j], ar[h][0], bj);
                    ffma2(acc[h][1][j], ar[h][1], bj);
                }
            }
        }
    }

    // Epilogue: + bias, 16 rows-slots x 8 cols per thread via float4 stores
    float4 bi0 = __ldg(reinterpret_cast<const float4*>(bias) + cg * 2);
    float4 bi1 = __ldg(reinterpret_cast<const float4*>(bias) + cg * 2 + 1);
    const int outbase = (n * M_ + m0) * FOUT;
    #pragma unroll
    for (int h = 0; h < 2; ++h) {
        #pragma unroll
        for (int p = 0; p < 2; ++p) {
            #pragma unroll
            for (int comp = 0; comp < 2; ++comp) {
                const int r = rg * 4 + h * 128 + 2 * p + comp;
                float* orow = out + outbase + r * FOUT + cg * 8;
                float4 v0, v1;
                v0.x = (comp ? acc[h][p][0].y : acc[h][p][0].x) + bi0.x;
                v0.y = (comp ? acc[h][p][1].y : acc[h][p][1].x) + bi0.y;
                v0.z = (comp ? acc[h][p][2].y : acc[h][p][2].x) + bi0.z;
                v0.w = (comp ? acc[h][p][3].y : acc[h][p][3].x) + bi0.w;
                v1.x = (comp ? acc[h][p][4].y : acc[h][p][4].x) + bi1.x;
                v1.y = (comp ? acc[h][p][5].y : acc[h][p][5].x) + bi1.y;
                v1.z = (comp ? acc[h][p][6].y : acc[h][p][6].x) + bi1.z;
                v1.w = (comp ? acc[h][p][7].y : acc[h][p][7].x) + bi1.w;
                reinterpret_cast<float4*>(orow)[0] = v0;
                reinterpret_cast<float4*>(orow)[1] = v1;
            }
        }
    }
}

extern "C" void kernel_launch(void* const* d_in, const int* in_sizes, int n_in,
                              void* d_out, int out_size)
{
    const float* x    = (const float*)d_in[0];   // (16, 65536, 32) f32
    const float* wgt  = (const float*)d_in[1];   // (7, 32, 32) f32
    const float* bias = (const float*)d_in[2];   // (32,) f32
    const int*   idx  = (const int*)  d_in[3];   // (65536*7,) i32
    const float* iv   = (const float*)d_in[4];   // (65536, 7) f32
    float* out = (float*)d_out;                  // (16, 65536, 32) f32

    dim3 grid(M_ / TILE_R, N_, 1);               // (256, 16)
    dim3 block(128, 1, 1);
    gfc_kernel<<<grid, block>>>(x, wgt, bias, idx, iv, out);
}